// round 11
// baseline (speedup 1.0000x reference)
#include <cuda_runtime.h>
#include <cuda_fp16.h>
#include <cstdint>

#define N_NODES  50000
#define N_GRAPHS 128
#define HID      512
#define QELEMS   (N_GRAPHS * HID)
#define NWALK    12
#define NODECAP  512                       // max nodes per graph (mean 391, 6-sigma safe)
#define ENTCAP   (NODECAP * NWALK)         // 6144 entries per graph slot
#define NSLICE   8
#define SEGCAP   (ENTCAP / NSLICE)         // 768 max entries per (g, slice)

// ---------------- device scratch ----------------
__device__ int   g_pb[N_NODES];
__device__ int   g_pos[N_NODES];
__device__ int   g_counts[N_GRAPHS];
__device__ int   g_ent[N_GRAPHS * ENTCAP];
__device__ int   g_ctr[4];
__device__ uint4 g_xh4[N_NODES * 64];      // x in fp16: 64 uint4 (512 halves) per row
__device__ float g_Qp[NSLICE * QELEMS];    // per-slice gather partials (no atomics)
__device__ float g_R0[QELEMS];
__device__ float g_R1[QELEMS];
__device__ float g_R2[QELEMS];
__device__ float g_P0[QELEMS];
__device__ float g_P1[QELEMS];

// ---------------- small zero: counters only (main stream) ----------------
__global__ void k_zero_small() {
    int i = threadIdx.x;
    if (i < N_GRAPHS) g_counts[i] = 0;
    if (i < 4) g_ctr[i] = 0;
}

// ---------------- zero R accumulators (forked stream, hidden under cvt) ----------------
__global__ void k_zeroR() {
    int i = blockIdx.x * blockDim.x + threadIdx.x;
    uint4 z = make_uint4(0, 0, 0, 0);
    if (i < 16384) {
        ((uint4*)g_R0)[i] = z;
        ((uint4*)g_R1)[i] = z;
        ((uint4*)g_R2)[i] = z;
    }
}

// ---------------- path_batch + histogram + position ----------------
__global__ void k_pb(const int* __restrict__ walk2, const int* __restrict__ batch) {
    int n = blockIdx.x * blockDim.x + threadIdx.x;
    if (n < N_NODES) {
        int g = batch[walk2[n]];           // walk2 row 0
        g_pb[n]  = g;
        g_pos[n] = atomicAdd(&g_counts[g], 1);
    }
}

// ---------------- build entry list: one thread per entry, fixed slots ----------------
__global__ void k_build(const int* __restrict__ w2, const int* __restrict__ w3,
                        const int* __restrict__ w4) {
    int e = blockIdx.x * blockDim.x + threadIdx.x;
    if (e >= N_NODES * NWALK) return;
    int n = e / NWALK;
    int r = e - n * NWALK;
    int j;
    if (r < 3)      j = w2[r * N_NODES + n];
    else if (r < 7) j = w3[(r - 3) * N_NODES + n];
    else            j = w4[(r - 7) * N_NODES + n];
    g_ent[g_pb[n] * ENTCAP + g_pos[n] * NWALK + r] = j;
}

// ---------------- convert x to fp16 (forked stream) ----------------
__global__ void k_cvt(const float* __restrict__ x) {
    int i = blockIdx.x * blockDim.x + threadIdx.x;
    if (i >= N_NODES * 64) return;
    const float4* x4 = (const float4*)x;
    float4 a = x4[2 * i];
    float4 b = x4[2 * i + 1];
    __half2 h0 = __floats2half2_rn(a.x, a.y);
    __half2 h1 = __floats2half2_rn(a.z, a.w);
    __half2 h2 = __floats2half2_rn(b.x, b.y);
    __half2 h3 = __floats2half2_rn(b.z, b.w);
    uint4 o;
    o.x = *(unsigned*)&h0; o.y = *(unsigned*)&h1;
    o.z = *(unsigned*)&h2; o.w = *(unsigned*)&h3;
    g_xh4[i] = o;
}

// ---------------- Q = A @ x : fp16 gather, smem-staged indices, MLP=8 ----------------
// grid (N_GRAPHS, NSLICE), 256 threads = 4 row-groups of 64 lanes.
__global__ __launch_bounds__(256)
void k_gather() {
    __shared__ int   s_idx[SEGCAP];
    __shared__ float s_red[4][512];

    const int g   = blockIdx.x;
    const int sl  = blockIdx.y;
    const int grp = threadIdx.x >> 6;
    const int c   = threadIdx.x & 63;
    const int tid = threadIdx.x;

    const int len = g_counts[g] * NWALK;
    const int s0  = (len * sl) / NSLICE;
    const int n   = (len * (sl + 1)) / NSLICE - s0;
    const int* seg = &g_ent[g * ENTCAP + s0];

    // stage indices coalesced into smem
    for (int i = tid; i < n; i += 256) s_idx[i] = seg[i];
    __syncthreads();

    float2 a0 = make_float2(0.f, 0.f), a1 = a0, a2 = a0, a3 = a0;

    int i = grp;
    for (; i + 28 < n; i += 32) {
        int j0 = s_idx[i];
        int j1 = s_idx[i + 4];
        int j2 = s_idx[i + 8];
        int j3 = s_idx[i + 12];
        int j4 = s_idx[i + 16];
        int j5 = s_idx[i + 20];
        int j6 = s_idx[i + 24];
        int j7 = s_idx[i + 28];
        uint4 v0 = g_xh4[j0 * 64 + c];
        uint4 v1 = g_xh4[j1 * 64 + c];
        uint4 v2 = g_xh4[j2 * 64 + c];
        uint4 v3 = g_xh4[j3 * 64 + c];
        uint4 v4 = g_xh4[j4 * 64 + c];
        uint4 v5 = g_xh4[j5 * 64 + c];
        uint4 v6 = g_xh4[j6 * 64 + c];
        uint4 v7 = g_xh4[j7 * 64 + c];
        #pragma unroll
        for (int q = 0; q < 8; q++) {
            uint4 v = (q == 0) ? v0 : (q == 1) ? v1 : (q == 2) ? v2 : (q == 3) ? v3
                    : (q == 4) ? v4 : (q == 5) ? v5 : (q == 6) ? v6 : v7;
            float2 f0 = __half22float2(*(__half2*)&v.x);
            float2 f1 = __half22float2(*(__half2*)&v.y);
            float2 f2 = __half22float2(*(__half2*)&v.z);
            float2 f3 = __half22float2(*(__half2*)&v.w);
            a0.x += f0.x; a0.y += f0.y;
            a1.x += f1.x; a1.y += f1.y;
            a2.x += f2.x; a2.y += f2.y;
            a3.x += f3.x; a3.y += f3.y;
        }
    }
    for (; i < n; i += 4) {
        int j = s_idx[i];
        uint4 v = g_xh4[j * 64 + c];
        float2 f0 = __half22float2(*(__half2*)&v.x);
        float2 f1 = __half22float2(*(__half2*)&v.y);
        float2 f2 = __half22float2(*(__half2*)&v.z);
        float2 f3 = __half22float2(*(__half2*)&v.w);
        a0.x += f0.x; a0.y += f0.y;
        a1.x += f1.x; a1.y += f1.y;
        a2.x += f2.x; a2.y += f2.y;
        a3.x += f3.x; a3.y += f3.y;
    }

    // cross-group smem reduce, then plain stores to this slice's partial buffer
    float* row = s_red[grp];
    row[c * 8 + 0] = a0.x; row[c * 8 + 1] = a0.y;
    row[c * 8 + 2] = a1.x; row[c * 8 + 3] = a1.y;
    row[c * 8 + 4] = a2.x; row[c * 8 + 5] = a2.y;
    row[c * 8 + 6] = a3.x; row[c * 8 + 7] = a3.y;
    __syncthreads();

    #pragma unroll
    for (int q = 0; q < 2; q++) {
        int col = tid + q * 256;
        float s = (s_red[0][col] + s_red[1][col]) + (s_red[2][col] + s_red[3][col]);
        g_Qp[sl * QELEMS + g * HID + col] = s;
    }
}

// ---------------- fused layer: R = A@W (split-K) ; grid-sync ; epilogue ----------------
// A may be split in nparts partial buffers of stride QELEMS (layer 0: 8, else 1).
#define GK 32
#define GN 64
__global__ __launch_bounds__(256)
void k_layer(const float* __restrict__ A, int nparts,
             const float* __restrict__ W, const float* __restrict__ bias,
             float* __restrict__ R, float* __restrict__ Pout,
             float* __restrict__ out, int layer) {
    __shared__ float sA[GK][129];
    __shared__ float sB[GK][GN];
    int nb = blockIdx.x;
    int kb = blockIdx.y;
    int tid = threadIdx.x;

    for (int i = tid; i < 128 * GK; i += 256) {
        int m = i >> 5;
        int k = i & 31;
        float v = 0.f;
        for (int p = 0; p < nparts; p++)
            v += A[p * QELEMS + m * HID + kb * GK + k];
        sA[k][m] = v;
    }
    for (int i = tid; i < GK * GN; i += 256) {
        int k = i >> 6;
        int cc = i & 63;
        sB[k][cc] = W[(kb * GK + k) * HID + nb * GN + cc];
    }
    __syncthreads();

    int trow = tid >> 4;
    int tcol = tid & 15;
    float acc[8][4];
    #pragma unroll
    for (int i = 0; i < 8; i++)
        #pragma unroll
        for (int jj = 0; jj < 4; jj++) acc[i][jj] = 0.f;

    #pragma unroll
    for (int k = 0; k < GK; k++) {
        float a[8], b[4];
        #pragma unroll
        for (int i = 0; i < 8; i++) a[i] = sA[k][trow * 8 + i];
        #pragma unroll
        for (int jj = 0; jj < 4; jj++) b[jj] = sB[k][tcol * 4 + jj];
        #pragma unroll
        for (int i = 0; i < 8; i++)
            #pragma unroll
            for (int jj = 0; jj < 4; jj++) acc[i][jj] += a[i] * b[jj];
    }

    #pragma unroll
    for (int i = 0; i < 8; i++)
        #pragma unroll
        for (int jj = 0; jj < 4; jj++)
            atomicAdd(&R[(trow * 8 + i) * HID + nb * GN + tcol * 4 + jj], acc[i][jj]);

    // grid-wide arrival (128 CTAs, all resident)
    __threadfence();
    __syncthreads();
    if (tid == 0) {
        atomicAdd(&g_ctr[layer], 1);
        while (atomicAdd(&g_ctr[layer], 0) < 128) __nanosleep(64);
    }
    __syncthreads();
    __threadfence();

    // epilogue: each CTA owns 512 contiguous elements
    int bid = blockIdx.y * 8 + blockIdx.x;
    #pragma unroll
    for (int t = tid; t < 512; t += 256) {
        int i = bid * 512 + t;
        int m = i >> 9;
        int c = i & 511;
        float cnt = (float)g_counts[m];
        float v = R[i] + 12.0f * cnt * bias[c];
        if (Pout) Pout[i] = v;
        out[m * (3 * HID) + layer * HID + c] = v / fmaxf(cnt, 1.0f);
    }
}

// ---------------- launch ----------------
extern "C" void kernel_launch(void* const* d_in, const int* in_sizes, int n_in,
                              void* d_out, int out_size) {
    const float* x     = (const float*)d_in[0];
    const int*   walk2 = (const int*)  d_in[1];
    const int*   walk3 = (const int*)  d_in[2];
    const int*   walk4 = (const int*)  d_in[3];
    const int*   batch = (const int*)  d_in[4];
    const float* W0 = (const float*)d_in[5];
    const float* b0 = (const float*)d_in[6];
    const float* W1 = (const float*)d_in[7];
    const float* b1 = (const float*)d_in[8];
    const float* W2 = (const float*)d_in[9];
    const float* b2 = (const float*)d_in[10];
    float* out = (float*)d_out;

    float *pQp, *pR0, *pR1, *pR2, *pP0, *pP1;
    cudaGetSymbolAddress((void**)&pQp, g_Qp);
    cudaGetSymbolAddress((void**)&pR0, g_R0);
    cudaGetSymbolAddress((void**)&pR1, g_R1);
    cudaGetSymbolAddress((void**)&pR2, g_R2);
    cudaGetSymbolAddress((void**)&pP0, g_P0);
    cudaGetSymbolAddress((void**)&pP1, g_P1);

    // fork: x->fp16 convert + R zero run concurrently with counts/pb/build
    cudaStream_t s2;
    cudaEvent_t eFork, eJoin;
    cudaStreamCreateWithFlags(&s2, cudaStreamNonBlocking);
    cudaEventCreateWithFlags(&eFork, cudaEventDisableTiming);
    cudaEventCreateWithFlags(&eJoin, cudaEventDisableTiming);

    cudaEventRecord(eFork, 0);
    cudaStreamWaitEvent(s2, eFork, 0);
    k_cvt<<<(N_NODES * 64 + 255) / 256, 256, 0, s2>>>(x);
    k_zeroR<<<64, 256, 0, s2>>>();
    cudaEventRecord(eJoin, s2);

    k_zero_small<<<1, 128>>>();
    k_pb<<<(N_NODES + 255) / 256, 256>>>(walk2, batch);
    k_build<<<(N_NODES * NWALK + 255) / 256, 256>>>(walk2, walk3, walk4);

    cudaStreamWaitEvent(0, eJoin, 0);
    k_gather<<<dim3(N_GRAPHS, NSLICE), 256>>>();

    k_layer<<<dim3(8, 16), 256>>>(pQp, NSLICE, W0, b0, pR0, pP0, out, 0);
    k_layer<<<dim3(8, 16), 256>>>(pP0, 1,      W1, b1, pR1, pP1, out, 1);
    k_layer<<<dim3(8, 16), 256>>>(pP1, 1,      W2, b2, pR2, nullptr, out, 2);

    cudaEventDestroy(eFork);
    cudaEventDestroy(eJoin);
    cudaStreamDestroy(s2);
}

// round 12
// speedup vs baseline: 1.1046x; 1.1046x over previous
#include <cuda_runtime.h>
#include <cuda_fp16.h>
#include <cstdint>

#define N_NODES  50000
#define N_GRAPHS 128
#define HID      512
#define QELEMS   (N_GRAPHS * HID)
#define NWALK    12
#define NODECAP  512                       // max nodes per graph (mean 391, 6-sigma safe)
#define ENTCAP   (NODECAP * NWALK)         // 6144 entries per graph slot
#define NSLICE   8

// ---------------- device scratch ----------------
__device__ int   g_counts[N_GRAPHS];
__device__ int   g_ent[N_GRAPHS * ENTCAP];
__device__ int   g_ctr[8];
__device__ uint4 g_xh4[N_NODES * 64];      // x in fp16: 64 uint4 (512 halves) per row
__device__ float g_Q[QELEMS];
__device__ float g_R0[QELEMS];
__device__ float g_R1[QELEMS];
__device__ float g_R2[QELEMS];
__device__ float g_P0[QELEMS];
__device__ float g_P1[QELEMS];

// ---------------- small zero: counters only (main stream) ----------------
__global__ void k_zero_small() {
    int i = threadIdx.x;
    if (i < N_GRAPHS) g_counts[i] = 0;
    if (i < 8) g_ctr[i] = 0;
}

// ---------------- zero Q + R accumulators (forked stream, hidden under cvt) ----------------
__global__ void k_zeroQR() {
    int i = blockIdx.x * blockDim.x + threadIdx.x;
    uint4 z = make_uint4(0, 0, 0, 0);
    if (i < 16384) {
        ((uint4*)g_Q)[i]  = z;
        ((uint4*)g_R0)[i] = z;
        ((uint4*)g_R1)[i] = z;
        ((uint4*)g_R2)[i] = z;
    }
}

// ---------------- fused pb+build: smem histogram + entry scatter ----------------
__global__ __launch_bounds__(256)
void k_pbb(const int* __restrict__ w2, const int* __restrict__ w3,
           const int* __restrict__ w4, const int* __restrict__ batch) {
    __shared__ int h[N_GRAPHS];
    __shared__ int base[N_GRAPHS];
    __shared__ int cur[N_GRAPHS];

    const int t = threadIdx.x;
    const int n = blockIdx.x * 256 + t;
    if (t < N_GRAPHS) { h[t] = 0; cur[t] = 0; }
    __syncthreads();

    int j[NWALK];
    int g = -1;
    if (n < N_NODES) {
        // prefetch all walk targets (independent loads, high MLP)
        j[0]  = w2[n];
        j[1]  = w2[N_NODES + n];
        j[2]  = w2[2 * N_NODES + n];
        j[3]  = w3[n];
        j[4]  = w3[N_NODES + n];
        j[5]  = w3[2 * N_NODES + n];
        j[6]  = w3[3 * N_NODES + n];
        j[7]  = w4[n];
        j[8]  = w4[N_NODES + n];
        j[9]  = w4[2 * N_NODES + n];
        j[10] = w4[3 * N_NODES + n];
        j[11] = w4[4 * N_NODES + n];
        g = batch[j[0]];                   // path_batch = batch[walk2[0][n]]
        atomicAdd(&h[g], 1);
    }
    __syncthreads();
    if (t < N_GRAPHS && h[t] > 0)
        base[t] = atomicAdd(&g_counts[t], h[t]);
    __syncthreads();
    if (n < N_NODES) {
        int pos = base[g] + atomicAdd(&cur[g], 1);
        int* dst = &g_ent[g * ENTCAP + pos * NWALK];
        #pragma unroll
        for (int r = 0; r < NWALK; r++) dst[r] = j[r];
    }
}

// ---------------- convert x to fp16 (forked stream) ----------------
__global__ void k_cvt(const float* __restrict__ x) {
    int i = blockIdx.x * blockDim.x + threadIdx.x;
    if (i >= N_NODES * 64) return;
    const float4* x4 = (const float4*)x;
    float4 a = x4[2 * i];
    float4 b = x4[2 * i + 1];
    __half2 h0 = __floats2half2_rn(a.x, a.y);
    __half2 h1 = __floats2half2_rn(a.z, a.w);
    __half2 h2 = __floats2half2_rn(b.x, b.y);
    __half2 h3 = __floats2half2_rn(b.z, b.w);
    uint4 o;
    o.x = *(unsigned*)&h0; o.y = *(unsigned*)&h1;
    o.z = *(unsigned*)&h2; o.w = *(unsigned*)&h3;
    g_xh4[i] = o;
}

// ---------------- Q = A @ x : fp16 gather, fp32 accumulate, MLP=8 ----------------
// grid (N_GRAPHS, NSLICE), 256 threads = 4 row-groups of 64 lanes.
__global__ __launch_bounds__(256)
void k_gather() {
    __shared__ float s_red[4][512];

    const int g   = blockIdx.x;
    const int sl  = blockIdx.y;
    const int grp = threadIdx.x >> 6;
    const int c   = threadIdx.x & 63;
    const int tid = threadIdx.x;

    const int start = g * ENTCAP;
    const int len   = g_counts[g] * NWALK;
    const int s0 = start + (len * sl) / NSLICE;
    const int s1 = start + (len * (sl + 1)) / NSLICE;

    float2 a0 = make_float2(0.f, 0.f), a1 = a0, a2 = a0, a3 = a0;

    int e = s0 + grp;
    for (; e + 28 < s1; e += 32) {
        int j0 = __ldg(&g_ent[e]);
        int j1 = __ldg(&g_ent[e + 4]);
        int j2 = __ldg(&g_ent[e + 8]);
        int j3 = __ldg(&g_ent[e + 12]);
        int j4 = __ldg(&g_ent[e + 16]);
        int j5 = __ldg(&g_ent[e + 20]);
        int j6 = __ldg(&g_ent[e + 24]);
        int j7 = __ldg(&g_ent[e + 28]);
        uint4 v0 = g_xh4[j0 * 64 + c];
        uint4 v1 = g_xh4[j1 * 64 + c];
        uint4 v2 = g_xh4[j2 * 64 + c];
        uint4 v3 = g_xh4[j3 * 64 + c];
        uint4 v4 = g_xh4[j4 * 64 + c];
        uint4 v5 = g_xh4[j5 * 64 + c];
        uint4 v6 = g_xh4[j6 * 64 + c];
        uint4 v7 = g_xh4[j7 * 64 + c];
        #pragma unroll
        for (int q = 0; q < 8; q++) {
            uint4 v = (q == 0) ? v0 : (q == 1) ? v1 : (q == 2) ? v2 : (q == 3) ? v3
                    : (q == 4) ? v4 : (q == 5) ? v5 : (q == 6) ? v6 : v7;
            float2 f0 = __half22float2(*(__half2*)&v.x);
            float2 f1 = __half22float2(*(__half2*)&v.y);
            float2 f2 = __half22float2(*(__half2*)&v.z);
            float2 f3 = __half22float2(*(__half2*)&v.w);
            a0.x += f0.x; a0.y += f0.y;
            a1.x += f1.x; a1.y += f1.y;
            a2.x += f2.x; a2.y += f2.y;
            a3.x += f3.x; a3.y += f3.y;
        }
    }
    for (; e < s1; e += 4) {
        int j = __ldg(&g_ent[e]);
        uint4 v = g_xh4[j * 64 + c];
        float2 f0 = __half22float2(*(__half2*)&v.x);
        float2 f1 = __half22float2(*(__half2*)&v.y);
        float2 f2 = __half22float2(*(__half2*)&v.z);
        float2 f3 = __half22float2(*(__half2*)&v.w);
        a0.x += f0.x; a0.y += f0.y;
        a1.x += f1.x; a1.y += f1.y;
        a2.x += f2.x; a2.y += f2.y;
        a3.x += f3.x; a3.y += f3.y;
    }

    // cross-group smem reduce, then 512 atomics per CTA
    float* row = s_red[grp];
    row[c * 8 + 0] = a0.x; row[c * 8 + 1] = a0.y;
    row[c * 8 + 2] = a1.x; row[c * 8 + 3] = a1.y;
    row[c * 8 + 4] = a2.x; row[c * 8 + 5] = a2.y;
    row[c * 8 + 6] = a3.x; row[c * 8 + 7] = a3.y;
    __syncthreads();

    #pragma unroll
    for (int q = 0; q < 2; q++) {
        int col = tid + q * 256;
        float s = (s_red[0][col] + s_red[1][col]) + (s_red[2][col] + s_red[3][col]);
        atomicAdd(&g_Q[g * HID + col], s);
    }
}

// ---------------- persistent fused 3-layer chain ----------------
// grid (8 nb, 16 kb) = 128 CTAs, all co-resident; counter grid-syncs between phases.
#define GK 32
#define GN 64

__device__ __forceinline__ void grid_sync(int ctr, int tid) {
    __threadfence();
    __syncthreads();
    if (tid == 0) {
        atomicAdd(&g_ctr[ctr], 1);
        while (atomicAdd(&g_ctr[ctr], 0) < 128) __nanosleep(32);
    }
    __syncthreads();
    __threadfence();
}

__global__ __launch_bounds__(256)
void k_layers(const float* __restrict__ W0, const float* __restrict__ b0,
              const float* __restrict__ W1, const float* __restrict__ b1,
              const float* __restrict__ W2, const float* __restrict__ b2,
              float* __restrict__ out) {
    __shared__ float sA[GK][129];
    __shared__ float sB[GK][GN];
    const int nb  = blockIdx.x;
    const int kb  = blockIdx.y;
    const int tid = threadIdx.x;
    const int bid = kb * 8 + nb;

    const float* As[3]  = { g_Q, g_P0, g_P1 };
    const float* Ws[3]  = { W0, W1, W2 };
    const float* bs[3]  = { b0, b1, b2 };
    float*       Rs[3]  = { g_R0, g_R1, g_R2 };
    float*       Ps[3]  = { g_P0, g_P1, nullptr };

    int ctr = 0;
    for (int L = 0; L < 3; L++) {
        const float* A = As[L];
        const float* W = Ws[L];
        float*       R = Rs[L];

        for (int i = tid; i < 128 * GK; i += 256) {
            int m = i >> 5;
            int k = i & 31;
            sA[k][m] = A[m * HID + kb * GK + k];
        }
        for (int i = tid; i < GK * GN; i += 256) {
            int k = i >> 6;
            int cc = i & 63;
            sB[k][cc] = W[(kb * GK + k) * HID + nb * GN + cc];
        }
        __syncthreads();

        int trow = tid >> 4;
        int tcol = tid & 15;
        float acc[8][4];
        #pragma unroll
        for (int i = 0; i < 8; i++)
            #pragma unroll
            for (int jj = 0; jj < 4; jj++) acc[i][jj] = 0.f;

        #pragma unroll
        for (int k = 0; k < GK; k++) {
            float a[8], b[4];
            #pragma unroll
            for (int i = 0; i < 8; i++) a[i] = sA[k][trow * 8 + i];
            #pragma unroll
            for (int jj = 0; jj < 4; jj++) b[jj] = sB[k][tcol * 4 + jj];
            #pragma unroll
            for (int i = 0; i < 8; i++)
                #pragma unroll
                for (int jj = 0; jj < 4; jj++) acc[i][jj] += a[i] * b[jj];
        }

        #pragma unroll
        for (int i = 0; i < 8; i++)
            #pragma unroll
            for (int jj = 0; jj < 4; jj++)
                atomicAdd(&R[(trow * 8 + i) * HID + nb * GN + tcol * 4 + jj], acc[i][jj]);

        grid_sync(ctr++, tid);

        // epilogue: each CTA owns 512 contiguous elements of R
        const float* bias = bs[L];
        float* Pout = Ps[L];
        #pragma unroll
        for (int t = tid; t < 512; t += 256) {
            int i = bid * 512 + t;
            int m = i >> 9;
            int c = i & 511;
            float cnt = (float)g_counts[m];
            float v = R[i] + 12.0f * cnt * bias[c];
            if (Pout) Pout[i] = v;
            out[m * (3 * HID) + L * HID + c] = v / fmaxf(cnt, 1.0f);
        }

        if (L < 2) grid_sync(ctr++, tid);   // P[L] must be complete before GEMM L+1
        __syncthreads();                    // protect sA/sB reuse
    }
}

// ---------------- launch ----------------
extern "C" void kernel_launch(void* const* d_in, const int* in_sizes, int n_in,
                              void* d_out, int out_size) {
    const float* x     = (const float*)d_in[0];
    const int*   walk2 = (const int*)  d_in[1];
    const int*   walk3 = (const int*)  d_in[2];
    const int*   walk4 = (const int*)  d_in[3];
    const int*   batch = (const int*)  d_in[4];
    const float* W0 = (const float*)d_in[5];
    const float* b0 = (const float*)d_in[6];
    const float* W1 = (const float*)d_in[7];
    const float* b1 = (const float*)d_in[8];
    const float* W2 = (const float*)d_in[9];
    const float* b2 = (const float*)d_in[10];
    float* out = (float*)d_out;

    // fork: x->fp16 convert + Q/R zero run concurrently with counters/pbb
    cudaStream_t s2;
    cudaEvent_t eFork, eJoin;
    cudaStreamCreateWithFlags(&s2, cudaStreamNonBlocking);
    cudaEventCreateWithFlags(&eFork, cudaEventDisableTiming);
    cudaEventCreateWithFlags(&eJoin, cudaEventDisableTiming);

    cudaEventRecord(eFork, 0);
    cudaStreamWaitEvent(s2, eFork, 0);
    k_cvt<<<(N_NODES * 64 + 255) / 256, 256, 0, s2>>>(x);
    k_zeroQR<<<64, 256, 0, s2>>>();
    cudaEventRecord(eJoin, s2);

    k_zero_small<<<1, 128>>>();
    k_pbb<<<(N_NODES + 255) / 256, 256>>>(walk2, walk3, walk4, batch);

    cudaStreamWaitEvent(0, eJoin, 0);
    k_gather<<<dim3(N_GRAPHS, NSLICE), 256>>>();

    k_layers<<<dim3(8, 16), 256>>>(W0, b0, W1, b1, W2, b2, out);

    cudaEventDestroy(eFork);
    cudaEventDestroy(eJoin);
    cudaStreamDestroy(s2);
}

// round 13
// speedup vs baseline: 1.1244x; 1.0179x over previous
#include <cuda_runtime.h>
#include <cuda_fp16.h>
#include <cstdint>

#define N_NODES  50000
#define N_GRAPHS 128
#define HID      512
#define QELEMS   (N_GRAPHS * HID)
#define NWALK    12
#define NODECAP  512                       // max nodes per graph (mean 391, 6-sigma safe)
#define ENTCAP   (NODECAP * NWALK)         // 6144 entries per graph slot
#define NSLICE   8

// ---------------- device scratch ----------------
__device__ int   g_counts[N_GRAPHS];
__device__ int   g_ent[N_GRAPHS * ENTCAP];
__device__ int   g_ctr[8];
__device__ uint4 g_xh4[N_NODES * 64];      // x in fp16: 64 uint4 (512 halves) per row
__device__ float g_Q[QELEMS];
__device__ float g_R0[QELEMS];
__device__ float g_R1[QELEMS];
__device__ float g_R2[QELEMS];
__device__ float g_P0[QELEMS];
__device__ float g_P1[QELEMS];

// ---------------- small zero: counters only ----------------
__global__ void k_zero_small() {
    int i = threadIdx.x;
    if (i < N_GRAPHS) g_counts[i] = 0;
    if (i < 8) g_ctr[i] = 0;
}

// ---------------- zero Q + R accumulators ----------------
__global__ void k_zeroQR() {
    int i = blockIdx.x * blockDim.x + threadIdx.x;
    uint4 z = make_uint4(0, 0, 0, 0);
    if (i < 16384) {
        ((uint4*)g_Q)[i]  = z;
        ((uint4*)g_R0)[i] = z;
        ((uint4*)g_R1)[i] = z;
        ((uint4*)g_R2)[i] = z;
    }
}

// ---------------- fused pb+build: smem histogram + entry scatter (128-thr blocks) ----------------
__global__ __launch_bounds__(128)
void k_pbb(const int* __restrict__ w2, const int* __restrict__ w3,
           const int* __restrict__ w4, const int* __restrict__ batch) {
    __shared__ int h[N_GRAPHS];
    __shared__ int base[N_GRAPHS];
    __shared__ int cur[N_GRAPHS];

    const int t = threadIdx.x;
    const int n = blockIdx.x * 128 + t;
    h[t] = 0; cur[t] = 0;
    __syncthreads();

    int j[NWALK];
    int g = -1;
    if (n < N_NODES) {
        j[0]  = w2[n];
        j[1]  = w2[N_NODES + n];
        j[2]  = w2[2 * N_NODES + n];
        j[3]  = w3[n];
        j[4]  = w3[N_NODES + n];
        j[5]  = w3[2 * N_NODES + n];
        j[6]  = w3[3 * N_NODES + n];
        j[7]  = w4[n];
        j[8]  = w4[N_NODES + n];
        j[9]  = w4[2 * N_NODES + n];
        j[10] = w4[3 * N_NODES + n];
        j[11] = w4[4 * N_NODES + n];
        g = batch[j[0]];                   // path_batch = batch[walk2[0][n]]
        atomicAdd(&h[g], 1);
    }
    __syncthreads();
    if (h[t] > 0)
        base[t] = atomicAdd(&g_counts[t], h[t]);
    __syncthreads();
    if (n < N_NODES) {
        int pos = base[g] + atomicAdd(&cur[g], 1);
        int* dst = &g_ent[g * ENTCAP + pos * NWALK];
        #pragma unroll
        for (int r = 0; r < NWALK; r++) dst[r] = j[r];
    }
}

// ---------------- convert x to fp16, one column-half (forked stream) ----------------
// half h covers fp32 columns [h*256, h*256+256) == uint4 indices [h*32, h*32+32) per row.
__global__ void k_cvt_half(const float* __restrict__ x, int h) {
    int i = blockIdx.x * blockDim.x + threadIdx.x;
    if (i >= N_NODES * 32) return;
    int row = i >> 5;
    int q   = i & 31;
    const float4* x4 = (const float4*)x;
    float4 a = x4[row * 128 + h * 64 + 2 * q];
    float4 b = x4[row * 128 + h * 64 + 2 * q + 1];
    __half2 h0 = __floats2half2_rn(a.x, a.y);
    __half2 h1 = __floats2half2_rn(a.z, a.w);
    __half2 h2 = __floats2half2_rn(b.x, b.y);
    __half2 h3 = __floats2half2_rn(b.z, b.w);
    uint4 o;
    o.x = *(unsigned*)&h0; o.y = *(unsigned*)&h1;
    o.z = *(unsigned*)&h2; o.w = *(unsigned*)&h3;
    g_xh4[row * 64 + h * 32 + q] = o;
}

// ---------------- Q += A @ x (one column-half): fp16 gather, MLP=8 ----------------
// grid (N_GRAPHS, NSLICE), 256 threads = 8 row-groups of 32 lanes.
// Lane c owns uint4 column (h*32 + c) = 8 Q columns.
__global__ __launch_bounds__(256)
void k_gather_half(int h) {
    __shared__ float s_red[8][256];

    const int g   = blockIdx.x;
    const int sl  = blockIdx.y;
    const int grp = threadIdx.x >> 5;
    const int c   = threadIdx.x & 31;
    const int tid = threadIdx.x;

    const int start = g * ENTCAP;
    const int len   = g_counts[g] * NWALK;
    const int s0 = start + (len * sl) / NSLICE;
    const int s1 = start + (len * (sl + 1)) / NSLICE;

    const uint4* __restrict__ xh = &g_xh4[h * 32];   // column-half base

    float2 a0 = make_float2(0.f, 0.f), a1 = a0, a2 = a0, a3 = a0;

    int e = s0 + grp;
    for (; e + 56 < s1; e += 64) {
        int j0 = __ldg(&g_ent[e]);
        int j1 = __ldg(&g_ent[e + 8]);
        int j2 = __ldg(&g_ent[e + 16]);
        int j3 = __ldg(&g_ent[e + 24]);
        int j4 = __ldg(&g_ent[e + 32]);
        int j5 = __ldg(&g_ent[e + 40]);
        int j6 = __ldg(&g_ent[e + 48]);
        int j7 = __ldg(&g_ent[e + 56]);
        uint4 v0 = xh[j0 * 64 + c];
        uint4 v1 = xh[j1 * 64 + c];
        uint4 v2 = xh[j2 * 64 + c];
        uint4 v3 = xh[j3 * 64 + c];
        uint4 v4 = xh[j4 * 64 + c];
        uint4 v5 = xh[j5 * 64 + c];
        uint4 v6 = xh[j6 * 64 + c];
        uint4 v7 = xh[j7 * 64 + c];
        #pragma unroll
        for (int q = 0; q < 8; q++) {
            uint4 v = (q == 0) ? v0 : (q == 1) ? v1 : (q == 2) ? v2 : (q == 3) ? v3
                    : (q == 4) ? v4 : (q == 5) ? v5 : (q == 6) ? v6 : v7;
            float2 f0 = __half22float2(*(__half2*)&v.x);
            float2 f1 = __half22float2(*(__half2*)&v.y);
            float2 f2 = __half22float2(*(__half2*)&v.z);
            float2 f3 = __half22float2(*(__half2*)&v.w);
            a0.x += f0.x; a0.y += f0.y;
            a1.x += f1.x; a1.y += f1.y;
            a2.x += f2.x; a2.y += f2.y;
            a3.x += f3.x; a3.y += f3.y;
        }
    }
    for (; e < s1; e += 8) {
        int j = __ldg(&g_ent[e]);
        uint4 v = xh[j * 64 + c];
        float2 f0 = __half22float2(*(__half2*)&v.x);
        float2 f1 = __half22float2(*(__half2*)&v.y);
        float2 f2 = __half22float2(*(__half2*)&v.z);
        float2 f3 = __half22float2(*(__half2*)&v.w);
        a0.x += f0.x; a0.y += f0.y;
        a1.x += f1.x; a1.y += f1.y;
        a2.x += f2.x; a2.y += f2.y;
        a3.x += f3.x; a3.y += f3.y;
    }

    // cross-group smem reduce (8 -> 1), then 256 atomics per CTA
    float* row = s_red[grp];
    row[c * 8 + 0] = a0.x; row[c * 8 + 1] = a0.y;
    row[c * 8 + 2] = a1.x; row[c * 8 + 3] = a1.y;
    row[c * 8 + 4] = a2.x; row[c * 8 + 5] = a2.y;
    row[c * 8 + 6] = a3.x; row[c * 8 + 7] = a3.y;
    __syncthreads();

    {
        int col = tid;                     // 0..255 within this half
        float s = ((s_red[0][col] + s_red[1][col]) + (s_red[2][col] + s_red[3][col]))
                + ((s_red[4][col] + s_red[5][col]) + (s_red[6][col] + s_red[7][col]));
        atomicAdd(&g_Q[g * HID + h * 256 + col], s);
    }
}

// ---------------- persistent fused 3-layer chain ----------------
#define GK 32
#define GN 64

__device__ __forceinline__ void grid_sync(int ctr, int tid) {
    __threadfence();
    __syncthreads();
    if (tid == 0) {
        atomicAdd(&g_ctr[ctr], 1);
        while (atomicAdd(&g_ctr[ctr], 0) < 128) __nanosleep(32);
    }
    __syncthreads();
    __threadfence();
}

__global__ __launch_bounds__(256)
void k_layers(const float* __restrict__ W0, const float* __restrict__ b0,
              const float* __restrict__ W1, const float* __restrict__ b1,
              const float* __restrict__ W2, const float* __restrict__ b2,
              float* __restrict__ out) {
    __shared__ float sA[GK][129];
    __shared__ float sB[GK][GN];
    const int nb  = blockIdx.x;
    const int kb  = blockIdx.y;
    const int tid = threadIdx.x;
    const int bid = kb * 8 + nb;

    const float* As[3]  = { g_Q, g_P0, g_P1 };
    const float* Ws[3]  = { W0, W1, W2 };
    const float* bs[3]  = { b0, b1, b2 };
    float*       Rs[3]  = { g_R0, g_R1, g_R2 };
    float*       Ps[3]  = { g_P0, g_P1, nullptr };

    int ctr = 0;
    for (int L = 0; L < 3; L++) {
        const float* A = As[L];
        const float* W = Ws[L];
        float*       R = Rs[L];

        for (int i = tid; i < 128 * GK; i += 256) {
            int m = i >> 5;
            int k = i & 31;
            sA[k][m] = A[m * HID + kb * GK + k];
        }
        for (int i = tid; i < GK * GN; i += 256) {
            int k = i >> 6;
            int cc = i & 63;
            sB[k][cc] = W[(kb * GK + k) * HID + nb * GN + cc];
        }
        __syncthreads();

        int trow = tid >> 4;
        int tcol = tid & 15;
        float acc[8][4];
        #pragma unroll
        for (int i = 0; i < 8; i++)
            #pragma unroll
            for (int jj = 0; jj < 4; jj++) acc[i][jj] = 0.f;

        #pragma unroll
        for (int k = 0; k < GK; k++) {
            float a[8], b[4];
            #pragma unroll
            for (int i = 0; i < 8; i++) a[i] = sA[k][trow * 8 + i];
            #pragma unroll
            for (int jj = 0; jj < 4; jj++) b[jj] = sB[k][tcol * 4 + jj];
            #pragma unroll
            for (int i = 0; i < 8; i++)
                #pragma unroll
                for (int jj = 0; jj < 4; jj++) acc[i][jj] += a[i] * b[jj];
        }

        #pragma unroll
        for (int i = 0; i < 8; i++)
            #pragma unroll
            for (int jj = 0; jj < 4; jj++)
                atomicAdd(&R[(trow * 8 + i) * HID + nb * GN + tcol * 4 + jj], acc[i][jj]);

        grid_sync(ctr++, tid);

        const float* bias = bs[L];
        float* Pout = Ps[L];
        #pragma unroll
        for (int t = tid; t < 512; t += 256) {
            int i = bid * 512 + t;
            int m = i >> 9;
            int c = i & 511;
            float cnt = (float)g_counts[m];
            float v = R[i] + 12.0f * cnt * bias[c];
            if (Pout) Pout[i] = v;
            out[m * (3 * HID) + L * HID + c] = v / fmaxf(cnt, 1.0f);
        }

        if (L < 2) grid_sync(ctr++, tid);
        __syncthreads();
    }
}

// ---------------- launch ----------------
extern "C" void kernel_launch(void* const* d_in, const int* in_sizes, int n_in,
                              void* d_out, int out_size) {
    const float* x     = (const float*)d_in[0];
    const int*   walk2 = (const int*)  d_in[1];
    const int*   walk3 = (const int*)  d_in[2];
    const int*   walk4 = (const int*)  d_in[3];
    const int*   batch = (const int*)  d_in[4];
    const float* W0 = (const float*)d_in[5];
    const float* b0 = (const float*)d_in[6];
    const float* W1 = (const float*)d_in[7];
    const float* b1 = (const float*)d_in[8];
    const float* W2 = (const float*)d_in[9];
    const float* b2 = (const float*)d_in[10];
    float* out = (float*)d_out;

    // fork: column-halved x->fp16 convert pipelined against the gather halves
    cudaStream_t s2;
    cudaEvent_t eFork, eH0, eH1;
    cudaStreamCreateWithFlags(&s2, cudaStreamNonBlocking);
    cudaEventCreateWithFlags(&eFork, cudaEventDisableTiming);
    cudaEventCreateWithFlags(&eH0, cudaEventDisableTiming);
    cudaEventCreateWithFlags(&eH1, cudaEventDisableTiming);

    cudaEventRecord(eFork, 0);
    cudaStreamWaitEvent(s2, eFork, 0);
    k_cvt_half<<<(N_NODES * 32 + 255) / 256, 256, 0, s2>>>(x, 0);
    cudaEventRecord(eH0, s2);
    k_cvt_half<<<(N_NODES * 32 + 255) / 256, 256, 0, s2>>>(x, 1);
    cudaEventRecord(eH1, s2);

    k_zero_small<<<1, 128>>>();
    k_pbb<<<(N_NODES + 127) / 128, 128>>>(walk2, walk3, walk4, batch);
    k_zeroQR<<<64, 256>>>();

    cudaStreamWaitEvent(0, eH0, 0);
    k_gather_half<<<dim3(N_GRAPHS, NSLICE), 256>>>(0);
    cudaStreamWaitEvent(0, eH1, 0);
    k_gather_half<<<dim3(N_GRAPHS, NSLICE), 256>>>(1);

    k_layers<<<dim3(8, 16), 256>>>(W0, b0, W1, b1, W2, b2, out);

    cudaEventDestroy(eFork);
    cudaEventDestroy(eH0);
    cudaEventDestroy(eH1);
    cudaStreamDestroy(s2);
}